// round 4
// baseline (speedup 1.0000x reference)
#include <cuda_runtime.h>

#define N_NODES 50000
#define N_EDGES 800000
#define IN_DIM 96
#define HID 32
#define OUT_DIM 64

#define SCAN_BLK 250
#define SCAN_CH  200   // 250*200 = 50000 exactly

// Scratch (device globals: allocation-free rule)
__device__ __align__(16) float g_xl[N_NODES * HID];        // x @ W1l
__device__ __align__(16) float g_hself[N_NODES * HID];     // x @ W1r + b1
__device__ __align__(16) float g_h[N_NODES * HID];         // relu(mean_agg(xl) + hself)
__device__ __align__(16) float g_agg2[N_NODES * HID];      // mean_agg(h)
__device__ int g_deg[N_NODES];
__device__ int g_off[N_NODES];
__device__ int g_cur[N_NODES];
__device__ int g_csr[N_EDGES];     // src node ids grouped by dst
__device__ int g_part[SCAN_BLK];

// ---------------------------------------------------------------------------
__global__ void k_zero_deg() {
    int i = blockIdx.x * blockDim.x + threadIdx.x;
    if (i < N_NODES) g_deg[i] = 0;
}

__global__ void k_hist(const int* __restrict__ ei) {
    int e = blockIdx.x * blockDim.x + threadIdx.x;
    if (e < N_EDGES) atomicAdd(&g_deg[ei[N_EDGES + e]], 1);
}

// ---- 3-phase exclusive scan of g_deg -> g_off ------------------------------
__global__ void k_scan1() {
    __shared__ int s[256];
    int t = threadIdx.x;
    int i = blockIdx.x * SCAN_CH + t;
    s[t] = (t < SCAN_CH) ? g_deg[i] : 0;
    __syncthreads();
    for (int d = 128; d > 0; d >>= 1) {
        if (t < d) s[t] += s[t + d];
        __syncthreads();
    }
    if (t == 0) g_part[blockIdx.x] = s[0];
}

__global__ void k_scan2() {
    __shared__ int s[256];
    int t = threadIdx.x;
    int v = (t < SCAN_BLK) ? g_part[t] : 0;
    s[t] = v;
    __syncthreads();
    for (int d = 1; d < 256; d <<= 1) {
        int add = (t >= d) ? s[t - d] : 0;
        __syncthreads();
        s[t] += add;
        __syncthreads();
    }
    if (t < SCAN_BLK) g_part[t] = s[t] - v;   // exclusive
}

__global__ void k_scan3() {
    __shared__ int s[256];
    int t = threadIdx.x;
    int i = blockIdx.x * SCAN_CH + t;
    int v = (t < SCAN_CH) ? g_deg[i] : 0;
    s[t] = v;
    __syncthreads();
    for (int d = 1; d < 256; d <<= 1) {
        int add = (t >= d) ? s[t - d] : 0;
        __syncthreads();
        s[t] += add;
        __syncthreads();
    }
    if (t < SCAN_CH) {
        int off = g_part[blockIdx.x] + s[t] - v;   // exclusive within block + base
        g_off[i] = off;
        g_cur[i] = off;
    }
}

__global__ void k_fill(const int* __restrict__ ei) {
    int e = blockIdx.x * blockDim.x + threadIdx.x;
    if (e >= N_EDGES) return;
    int pos = atomicAdd(&g_cur[ei[N_EDGES + e]], 1);
    g_csr[pos] = ei[e];
}

// ---------------------------------------------------------------------------
// GEMM1: [N,96] x [96,32] (two weight matrices). Block = 256 thr = 32 cols x
// 8 warps, each thread does 4 rows -> 32 rows/block. Weights in smem.
__global__ void k_gemm1(const float* __restrict__ x,
                        const float* __restrict__ Wl,
                        const float* __restrict__ Wr,
                        const float* __restrict__ b) {
    __shared__ float sL[IN_DIM * HID];
    __shared__ float sR[IN_DIM * HID];
    __shared__ float sb[HID];
    int t = threadIdx.x;
    for (int i = t; i < IN_DIM * HID; i += 256) { sL[i] = Wl[i]; sR[i] = Wr[i]; }
    if (t < HID) sb[t] = b[t];
    __syncthreads();

    int col  = t & 31;
    int wy   = t >> 5;                 // 0..7
    int row0 = blockIdx.x * 32 + wy * 4;

    float aL[4], aR[4];
    int rr[4];
#pragma unroll
    for (int r = 0; r < 4; r++) {
        aL[r] = 0.f; aR[r] = sb[col];
        rr[r] = min(row0 + r, N_NODES - 1);   // clamp reads; guard stores
    }
#pragma unroll 4
    for (int k = 0; k < IN_DIM; k++) {
        float wl = sL[k * HID + col];
        float wr = sR[k * HID + col];
#pragma unroll
        for (int r = 0; r < 4; r++) {
            float xv = x[rr[r] * IN_DIM + k];   // warp-uniform -> broadcast
            aL[r] += xv * wl;
            aR[r] += xv * wr;
        }
    }
#pragma unroll
    for (int r = 0; r < 4; r++) {
        int row = row0 + r;
        if (row < N_NODES) {
            g_xl[row * HID + col]    = aL[r];
            g_hself[row * HID + col] = aR[r];
        }
    }
}

// ---------------------------------------------------------------------------
// agg1 (gather): one warp per dst node, lane = feature column.
// g_h = relu(mean_{src} g_xl[src] + g_hself[node])
__global__ void k_agg1() {
    int node = (blockIdx.x * blockDim.x + threadIdx.x) >> 5;
    if (node >= N_NODES) return;
    int lane  = threadIdx.x & 31;
    int start = g_off[node];
    int deg   = g_deg[node];
    float acc = 0.f;
    int j = 0;
    for (; j + 1 < deg; j += 2) {           // MLP=2
        int s0 = g_csr[start + j];
        int s1 = g_csr[start + j + 1];
        float v0 = g_xl[s0 * HID + lane];
        float v1 = g_xl[s1 * HID + lane];
        acc += v0 + v1;
    }
    if (j < deg) acc += g_xl[g_csr[start + j] * HID + lane];
    float v = acc / fmaxf((float)deg, 1.0f) + g_hself[node * HID + lane];
    g_h[node * HID + lane] = fmaxf(v, 0.f);
}

// ---------------------------------------------------------------------------
// agg2 (gather): g_agg2 = mean_{src} g_h[src]
__global__ void k_agg2() {
    int node = (blockIdx.x * blockDim.x + threadIdx.x) >> 5;
    if (node >= N_NODES) return;
    int lane  = threadIdx.x & 31;
    int start = g_off[node];
    int deg   = g_deg[node];
    float acc = 0.f;
    int j = 0;
    for (; j + 1 < deg; j += 2) {
        int s0 = g_csr[start + j];
        int s1 = g_csr[start + j + 1];
        float v0 = g_h[s0 * HID + lane];
        float v1 = g_h[s1 * HID + lane];
        acc += v0 + v1;
    }
    if (j < deg) acc += g_h[g_csr[start + j] * HID + lane];
    g_agg2[node * HID + lane] = acc / fmaxf((float)deg, 1.0f);
}

// ---------------------------------------------------------------------------
// Fused layer-2 GEMM + epilogue: out = agg2 @ W2l + h @ W2r + b2
// (agg2 is already the mean.) Block = 256 thr = 64 cols x 4 row-groups.
__global__ void k_gemm2_final(const float* __restrict__ Wl,
                              const float* __restrict__ Wr,
                              const float* __restrict__ b,
                              float* __restrict__ out) {
    __shared__ float sL[HID * OUT_DIM];
    __shared__ float sR[HID * OUT_DIM];
    __shared__ float sb[OUT_DIM];
    int t = threadIdx.x;
    for (int i = t; i < HID * OUT_DIM; i += 256) { sL[i] = Wl[i]; sR[i] = Wr[i]; }
    if (t < OUT_DIM) sb[t] = b[t];
    __syncthreads();

    int col  = t & 63;
    int wy   = t >> 6;                  // 0..3
    int row0 = blockIdx.x * 16 + wy * 4;

    float acc[4];
#pragma unroll
    for (int r = 0; r < 4; r++) acc[r] = sb[col];
#pragma unroll 4
    for (int k = 0; k < HID; k++) {
        float wl = sL[k * OUT_DIM + col];
        float wr = sR[k * OUT_DIM + col];
#pragma unroll
        for (int r = 0; r < 4; r++) {
            float am = g_agg2[(row0 + r) * HID + k];   // warp-uniform
            float hv = g_h[(row0 + r) * HID + k];      // warp-uniform
            acc[r] += am * wl + hv * wr;
        }
    }
#pragma unroll
    for (int r = 0; r < 4; r++)
        out[(row0 + r) * OUT_DIM + col] = acc[r];
}

// ---------------------------------------------------------------------------
extern "C" void kernel_launch(void* const* d_in, const int* in_sizes, int n_in,
                              void* d_out, int out_size) {
    const float* x   = (const float*)d_in[0];
    const int*   ei  = (const int*)d_in[1];
    const float* W1l = (const float*)d_in[2];
    const float* W1r = (const float*)d_in[3];
    const float* b1  = (const float*)d_in[4];
    const float* W2l = (const float*)d_in[5];
    const float* W2r = (const float*)d_in[6];
    const float* b2  = (const float*)d_in[7];
    float* out = (float*)d_out;

    // CSR build
    k_zero_deg<<<(N_NODES + 255) / 256, 256>>>();
    k_hist<<<(N_EDGES + 255) / 256, 256>>>(ei);
    k_scan1<<<SCAN_BLK, 256>>>();
    k_scan2<<<1, 256>>>();
    k_scan3<<<SCAN_BLK, 256>>>();
    k_fill<<<(N_EDGES + 255) / 256, 256>>>(ei);

    // Layer 1
    k_gemm1<<<(N_NODES + 31) / 32, 256>>>(x, W1l, W1r, b1);
    k_agg1<<<(N_NODES * 32 + 255) / 256, 256>>>();

    // Layer 2
    k_agg2<<<(N_NODES * 32 + 255) / 256, 256>>>();
    k_gemm2_final<<<N_NODES / 16, 256>>>(W2l, W2r, b2, out);
}